// round 16
// baseline (speedup 1.0000x reference)
#include <cuda_runtime.h>

// RegRankLoss, ONE fused kernel: counting-sort by target -> MLP-32 rank-merge
// -> 2-op pair loop (2 tile-pairs per block).
// After ascending sort by t, sorted a<b: term = softplus(p_a-p_b)
//   = ln2*log2(1 + F_a*G_b), F=exp2(p*log2e), G=exp2(-p*log2e)
// loss = ln2*S/(N(N-1)/2). Ties: measure-zero (validated rel_err 6.65e-8).
// 264 blocks @ 256thr, __launch_bounds__(256,2) -> all co-resident (<=296).

#define NT    256
#define TILE  256
#define NCH   32          // 8192/256 chunks
#define GRIDB 264         // blocks; each handles 2 of 528 tile-pairs
#define MAXB  512

typedef unsigned long long ull;

__device__ ull      g_runs[8192];
__device__ float    g_F[8192];
__device__ float    g_G[8192];
__device__ float    g_ps[MAXB];
__device__ unsigned g_bar[2];     // spin-barrier counters (reset by finalize)
__device__ unsigned g_done;       // ticket (reset by finalize)

__device__ __forceinline__ float fast_ex2(float x) {
    float r; asm("ex2.approx.f32 %0, %1;" : "=f"(r) : "f"(x)); return r;
}
__device__ __forceinline__ float fast_lg2(float x) {
    float r; asm("lg2.approx.f32 %0, %1;" : "=f"(r) : "f"(x)); return r;
}

__device__ __forceinline__ void grid_bar(int slot, unsigned total, int tid) {
    __syncthreads();
    __threadfence();
    if (tid == 0) {
        atomicAdd(&g_bar[slot], 1u);
        while (*(volatile unsigned*)&g_bar[slot] < total) __nanosleep(64);
    }
    __syncthreads();
    __threadfence();
}

__global__ __launch_bounds__(NT, 2) void rrl_fused(
    const float* __restrict__ pred,
    const float* __restrict__ target,
    int n_tiles,                   // 32
    float* __restrict__ out, double inv_cnt)
{
    const int b   = blockIdx.x;
    const int tid = threadIdx.x;
    __shared__ ull skey[TILE];                 // phase0 keys; phase2 aliased as sG
    float* sG = (float*)skey;

    // ---------- Phase 0: counting-sort each 256-chunk by target ----------
    if (b < NCH) {
        int base = b * TILE;
        unsigned tb = __float_as_uint(target[base + tid]);
        tb ^= (tb & 0x80000000u) ? 0xFFFFFFFFu : 0x80000000u;   // monotone flip
        skey[tid] = ((ull)tb << 32) | (unsigned)(base + tid);   // unique keys
        __syncthreads();

        ull x = skey[tid];
        int rank = 0;
        const ulonglong2* kv = (const ulonglong2*)skey;
        #pragma unroll 8
        for (int j = 0; j < TILE / 2; ++j) {
            ulonglong2 k2 = kv[j];              // broadcast LDS.128
            rank += (k2.x < x) + (k2.y < x);
        }
        g_runs[base + rank] = x;
    }
    grid_bar(0, GRIDB, tid);

    // ---------- Phase 1: global rank, ALL 32 runs in lockstep (MLP=32) ----
    if (b < NCH) {
        int g = b * TILE + tid;
        ull x = __ldcg(&g_runs[g]);
        int pos[NCH];
        #pragma unroll
        for (int s = 0; s < NCH; ++s) pos[s] = 0;
        #pragma unroll
        for (int w = TILE / 2; w >= 1; w >>= 1) {   // 8 dependent steps
            #pragma unroll
            for (int s = 0; s < NCH; ++s)
                if (__ldcg(&g_runs[s * TILE + pos[s] + w - 1]) < x) pos[s] += w;
        }
        int rank = 0;
        #pragma unroll
        for (int s = 0; s < NCH; ++s) {             // 9th step (lower_bound fixup)
            if (__ldcg(&g_runs[s * TILE + pos[s]]) < x) ++pos[s];
            rank += pos[s];
        }
        int idx = (int)(unsigned)(x & 0xFFFFFFFFu);
        float ps = pred[idx] * 1.44269504088896340736f;
        g_F[rank] = fast_ex2(ps);
        g_G[rank] = fast_ex2(-ps);
    }
    grid_bar(1, GRIDB, tid);

    // ---------- Phase 2: two tile-pairs per block over sorted F/G ----------
    float acc = 0.0f;

    #pragma unroll 1
    for (int pp = 0; pp < 2; ++pp) {
        int pid = b + pp * GRIDB;                  // 0..527
        int I = 0, rem = pid;
        while (rem >= n_tiles - I) { rem -= n_tiles - I; ++I; }
        int J = I + rem;

        __syncthreads();                           // protect sG reuse
        sG[tid] = __ldcg(&g_G[J * TILE + tid]);
        float Fi = __ldcg(&g_F[I * TILE + tid]);
        __syncthreads();

        if (I != J) {
            const float4* Gv = reinterpret_cast<const float4*>(sG);
            #pragma unroll
            for (int g = 0; g < TILE / 8; ++g) {
                float4 a = Gv[2 * g], c = Gv[2 * g + 1];
                float pa = 1.0f, pb = 1.0f;
                pa = __fmaf_rn(pa, Fi * a.x, pa); pb = __fmaf_rn(pb, Fi * a.y, pb);
                pa = __fmaf_rn(pa, Fi * a.z, pa); pb = __fmaf_rn(pb, Fi * a.w, pb);
                pa = __fmaf_rn(pa, Fi * c.x, pa); pb = __fmaf_rn(pb, Fi * c.y, pb);
                pa = __fmaf_rn(pa, Fi * c.z, pa); pb = __fmaf_rn(pb, Fi * c.w, pb);
                acc += fast_lg2(pa * pb);
            }
        } else {
            float prod = 1.0f;
            int c8 = 0;
            for (int j = tid + 1; j < TILE; ++j) {
                prod = __fmaf_rn(prod, Fi * sG[j], prod);
                if (++c8 == 8) { acc += fast_lg2(prod); prod = 1.0f; c8 = 0; }
            }
            acc += fast_lg2(prod);
        }
    }

    // ---- block reduction (8 warps) ----
    #pragma unroll
    for (int off = 16; off > 0; off >>= 1)
        acc += __shfl_down_sync(0xffffffffu, acc, off);

    __shared__ float s_a[8];
    __shared__ int s_last;
    int wid = tid >> 5, lid = tid & 31;
    if (lid == 0) s_a[wid] = acc;
    __syncthreads();

    if (tid == 0) {
        float a = 0.0f;
        #pragma unroll
        for (int w = 0; w < 8; ++w) a += s_a[w];
        g_ps[b] = a;
        __threadfence();
        unsigned ticket = atomicAdd(&g_done, 1u);
        s_last = (ticket == GRIDB - 1) ? 1 : 0;
    }
    __syncthreads();

    // ---- last block finalizes + resets sync state for graph replay ----
    if (s_last) {
        double ds = 0.0;
        for (int s = tid; s < GRIDB; s += NT)
            ds += (double)(*(volatile float*)&g_ps[s]);
        #pragma unroll
        for (int off = 16; off > 0; off >>= 1)
            ds += __shfl_down_sync(0xffffffffu, ds, off);
        __shared__ double f_s[8];
        if (lid == 0) f_s[wid] = ds;
        __syncthreads();
        if (tid == 0) {
            double S = 0.0;
            #pragma unroll
            for (int w = 0; w < 8; ++w) S += f_s[w];
            const double LN2 = 0.69314718055994530942;
            out[0] = (float)(LN2 * S * inv_cnt);
            __threadfence();
            g_done   = 0u;
            g_bar[0] = 0u;
            g_bar[1] = 0u;
        }
    }
}

extern "C" void kernel_launch(void* const* d_in, const int* in_sizes, int n_in,
                              void* d_out, int out_size) {
    const float* pred   = (const float*)d_in[0];
    const float* target = (const float*)d_in[1];
    float* out = (float*)d_out;

    int n = in_sizes[0];                          // 8192
    int n_tiles = n / TILE;                       // 32

    double cnt = (double)n * (double)(n - 1) * 0.5;
    double inv_cnt = 1.0 / cnt;

    rrl_fused<<<GRIDB, NT>>>(pred, target, n_tiles, out, inv_cnt);
}

// round 17
// speedup vs baseline: 1.0972x; 1.0972x over previous
#include <cuda_runtime.h>

// RegRankLoss, 2 kernels: per-chunk counting sort -> region-split pair kernel.
// Chunks of 256 sorted by t. For pair (i,j): term/ln2 = log2(1 + e),
//   e = (tj<ti) ? Gi*Fj : Fi*Gj,  F = exp2(p*log2e), G = exp2(-p*log2e).
// Both tiles chunk-sorted => warp-uniform split bounds; middle band only uses
// per-pair select. loss = ln2*S/(N(N-1)/2); ties-as-ordered (validated 6.65e-8).

#define NT    256
#define TILE  256
#define NCH   32
#define MAXB  1024

typedef unsigned long long ull;

__device__ float    g_T[8192];
__device__ float    g_Fv[8192];
__device__ float    g_Gv[8192];
__device__ float    g_ps[MAXB];
__device__ unsigned g_done;     // zero-init; reset by finalize

__device__ __forceinline__ float fast_ex2(float x) {
    float r; asm("ex2.approx.f32 %0, %1;" : "=f"(r) : "f"(x)); return r;
}
__device__ __forceinline__ float fast_lg2(float x) {
    float r; asm("lg2.approx.f32 %0, %1;" : "=f"(r) : "f"(x)); return r;
}

// ---------- K1: counting-sort each 256-chunk by target ----------
__global__ __launch_bounds__(NT) void sort_chunks(
    const float* __restrict__ pred, const float* __restrict__ target)
{
    __shared__ ull skey[TILE];
    int base = blockIdx.x * TILE;
    int tid = threadIdx.x;

    float tval = target[base + tid];
    unsigned tb = __float_as_uint(tval);
    tb ^= (tb & 0x80000000u) ? 0xFFFFFFFFu : 0x80000000u;   // monotone flip
    skey[tid] = ((ull)tb << 32) | (unsigned)tid;            // unique key
    __syncthreads();

    ull x = skey[tid];
    int rank = 0;
    const ulonglong2* kv = (const ulonglong2*)skey;
    #pragma unroll 8
    for (int j = 0; j < TILE / 2; ++j) {
        ulonglong2 k2 = kv[j];
        rank += (k2.x < x) + (k2.y < x);
    }

    float ps = pred[base + tid] * 1.44269504088896340736f;
    g_T [base + rank] = tval;
    g_Fv[base + rank] = fast_ex2(ps);
    g_Gv[base + rank] = fast_ex2(-ps);
}

// ---------- K2: pair kernel with warp-uniform region split ----------
__global__ __launch_bounds__(NT) void rrl_pairs(
    int n_tiles, int n_blocks, float* __restrict__ out, double inv_cnt)
{
    int b = blockIdx.x;
    int I = 0, rem = b;
    while (rem >= n_tiles - I) { rem -= n_tiles - I; ++I; }
    int J = I + rem;

    __shared__ __align__(16) float sT[TILE];
    __shared__ __align__(16) float sF[TILE];
    __shared__ __align__(16) float sG[TILE];

    const int tid = threadIdx.x;
    {
        int jg = J * TILE + tid;
        sT[tid] = g_T[jg]; sF[tid] = g_Fv[jg]; sG[tid] = g_Gv[jg];
    }
    int ig = I * TILE + tid;
    float ti = g_T[ig];
    float Fi = g_Fv[ig];
    float Gi = g_Gv[ig];
    __syncthreads();

    float acc = 0.0f;

    if (I != J) {
        // per-lane split s = #{ sT[j] < ti }  (branchless lower_bound, 8 steps)
        int s = 0;
        #pragma unroll
        for (int w = TILE / 2; w >= 1; w >>= 1)
            if (sT[s + w - 1] < ti) s += w;

        int s_lo = __shfl_sync(0xffffffffu, s, 0);
        int s_hi = __shfl_sync(0xffffffffu, s, 31);
        int r0 = s_lo & ~7;
        int r1 = (s_hi + 7) & ~7; if (r1 > TILE) r1 = TILE;

        const float4* Fv = reinterpret_cast<const float4*>(sF);
        const float4* Gv = reinterpret_cast<const float4*>(sG);

        // Loop A: j < r0 -> all lanes tj < ti : factor Gi*Fj
        for (int j = 0; j < r0; j += 8) {
            float4 a = Fv[j >> 2], c = Fv[(j >> 2) + 1];
            float pa = 1.0f, pb = 1.0f;
            pa = __fmaf_rn(pa, Gi * a.x, pa); pb = __fmaf_rn(pb, Gi * a.y, pb);
            pa = __fmaf_rn(pa, Gi * a.z, pa); pb = __fmaf_rn(pb, Gi * a.w, pb);
            pa = __fmaf_rn(pa, Gi * c.x, pa); pb = __fmaf_rn(pb, Gi * c.y, pb);
            pa = __fmaf_rn(pa, Gi * c.z, pa); pb = __fmaf_rn(pb, Gi * c.w, pb);
            acc += fast_lg2(pa * pb);
        }
        // Loop B: mixed band, per-pair select
        for (int j = r0; j < r1; j += 8) {
            float pa = 1.0f, pb = 1.0f;
            #pragma unroll
            for (int k = 0; k < 8; k += 2) {
                float t0 = sT[j + k],     t1 = sT[j + k + 1];
                float f0 = (t0 < ti) ? Gi * sF[j + k]     : Fi * sG[j + k];
                float f1 = (t1 < ti) ? Gi * sF[j + k + 1] : Fi * sG[j + k + 1];
                pa = __fmaf_rn(pa, f0, pa);
                pb = __fmaf_rn(pb, f1, pb);
            }
            acc += fast_lg2(pa * pb);
        }
        // Loop C: j >= r1 -> all lanes tj >= ti : factor Fi*Gj
        for (int j = r1; j < TILE; j += 8) {
            float4 a = Gv[j >> 2], c = Gv[(j >> 2) + 1];
            float pa = 1.0f, pb = 1.0f;
            pa = __fmaf_rn(pa, Fi * a.x, pa); pb = __fmaf_rn(pb, Fi * a.y, pb);
            pa = __fmaf_rn(pa, Fi * a.z, pa); pb = __fmaf_rn(pb, Fi * a.w, pb);
            pa = __fmaf_rn(pa, Fi * c.x, pa); pb = __fmaf_rn(pb, Fi * c.y, pb);
            pa = __fmaf_rn(pa, Fi * c.z, pa); pb = __fmaf_rn(pb, Fi * c.w, pb);
            acc += fast_lg2(pa * pb);
        }
    } else {
        // Diagonal: chunk sorted ascending => j > tid implies tj >= ti.
        // term = log2(1 + Fi*Gj); flush lg2 every 8 (uniform j, per-lane entry).
        float prod = 1.0f;
        for (int j = tid + 1; j < TILE; ++j) {
            prod = __fmaf_rn(prod, Fi * sG[j], prod);
            if ((j & 7) == 7) { acc += fast_lg2(prod); prod = 1.0f; }
        }
        acc += fast_lg2(prod);
    }

    // ---- block reduction (8 warps) ----
    #pragma unroll
    for (int off = 16; off > 0; off >>= 1)
        acc += __shfl_down_sync(0xffffffffu, acc, off);

    __shared__ float s_a[8];
    __shared__ int s_last;
    int wid = tid >> 5, lid = tid & 31;
    if (lid == 0) s_a[wid] = acc;
    __syncthreads();

    if (tid == 0) {
        float a = 0.0f;
        #pragma unroll
        for (int w = 0; w < 8; ++w) a += s_a[w];
        g_ps[b] = a;
        __threadfence();
        unsigned ticket = atomicAdd(&g_done, 1u);
        s_last = (ticket == (unsigned)(n_blocks - 1)) ? 1 : 0;
    }
    __syncthreads();

    if (s_last) {
        double ds = 0.0;
        for (int s2 = tid; s2 < n_blocks; s2 += NT)
            ds += (double)(*(volatile float*)&g_ps[s2]);
        #pragma unroll
        for (int off = 16; off > 0; off >>= 1)
            ds += __shfl_down_sync(0xffffffffu, ds, off);
        __shared__ double f_s[8];
        if (lid == 0) f_s[wid] = ds;
        __syncthreads();
        if (tid == 0) {
            double S = 0.0;
            #pragma unroll
            for (int w = 0; w < 8; ++w) S += f_s[w];
            const double LN2 = 0.69314718055994530942;
            out[0] = (float)(LN2 * S * inv_cnt);
            __threadfence();
            g_done = 0u;
        }
    }
}

extern "C" void kernel_launch(void* const* d_in, const int* in_sizes, int n_in,
                              void* d_out, int out_size) {
    const float* pred   = (const float*)d_in[0];
    const float* target = (const float*)d_in[1];
    float* out = (float*)d_out;

    int n = in_sizes[0];                          // 8192
    int n_tiles  = n / TILE;                      // 32
    int n_blocks = n_tiles * (n_tiles + 1) / 2;   // 528

    double cnt = (double)n * (double)(n - 1) * 0.5;
    double inv_cnt = 1.0 / cnt;

    sort_chunks<<<n / TILE, NT>>>(pred, target);
    rrl_pairs<<<n_blocks, NT>>>(n_tiles, n_blocks, out, inv_cnt);
}